// round 11
// baseline (speedup 1.0000x reference)
#include <cuda_runtime.h>
#include <cuda_bf16.h>
#include <cstdint>

#define BB 512
#define LL 2048
#define CC 32

// Device scratch (no allocation allowed)
__device__ double g_logz[BB];
__device__ double g_score[BB];
__device__ float  g_w[BB * CC];   // forward half-vector
__device__ float  g_u[BB * CC];   // backward half-vector
__device__ float  g_mf[BB];       // forward log2-scale
__device__ float  g_mb[BB];       // backward log2-scale
__device__ int    g_bt[BB];       // per-batch merge ticket
__device__ int    g_ticket;       // global completion ticket

__device__ __forceinline__ float rcp_approx(float x) {
    float r; asm("rcp.approx.f32 %0, %1;" : "=f"(r) : "f"(x)); return r;
}
__device__ __forceinline__ float ex2_approx(float x) {
    float r; asm("ex2.approx.f32 %0, %1;" : "=f"(r) : "f"(x)); return r;
}
__device__ __forceinline__ float lg2_approx(float x) {
    float r; asm("lg2.approx.f32 %0, %1;" : "=f"(r) : "f"(x)); return r;
}
// pack(lo, hi) -> bf16x2 reg (hi in [31:16], lo in [15:0])
__device__ __forceinline__ uint32_t pack_bf16(float lo, float hi) {
    uint32_t r;
    asm("cvt.rn.satfinite.bf16x2.f32 %0, %1, %2;" : "=r"(r) : "f"(hi), "f"(lo));
    return r;
}
// Full m16n8k16 bf16 MMA: rows 0-7 = batch0 (a0,a2), rows 8-15 = batch1 (a1,a3).
// d0,d1 = batch0 (row gid), d2,d3 = batch1 (row gid+8); cols 2tid,2tid+1 per n-tile.
__device__ __forceinline__ void mma16(float& d0, float& d1, float& d2, float& d3,
    uint32_t a0, uint32_t a1, uint32_t a2, uint32_t a3,
    uint32_t b0, uint32_t b1, float c0, float c1, float c2, float c3)
{
    asm("mma.sync.aligned.m16n8k16.row.col.f32.bf16.bf16.f32 "
        "{%0,%1,%2,%3}, {%4,%5,%6,%7}, {%8,%9}, {%10,%11,%12,%13};"
        : "=f"(d0), "=f"(d1), "=f"(d2), "=f"(d3)
        : "r"(a0), "r"(a1), "r"(a2), "r"(a3),
          "r"(b0), "r"(b1),
          "f"(c0), "f"(c1), "f"(c2), "f"(c3));
}

#define LOG2E 1.4426950408889634f
#define FULLM 0xffffffffu

// Prepare exp(emission) fragments for BOTH batches for the next step:
// 2 warp-wide ex2 + 16 SHFL.IDX, one step ahead -> off the MMA critical path.
#define PREPE2(RAW0_, RAW1_) do {                                             \
    float exa_ = ex2_approx((RAW0_) * LOG2E);                                 \
    float exb_ = ex2_approx((RAW1_) * LOG2E);                                 \
    ef[0] = __shfl_sync(FULLM, exa_, s0);      ef[1] = __shfl_sync(FULLM, exa_, s1);      \
    ef[2] = __shfl_sync(FULLM, exa_, s0 + 8);  ef[3] = __shfl_sync(FULLM, exa_, s1 + 8);  \
    ef[4] = __shfl_sync(FULLM, exa_, s0 + 16); ef[5] = __shfl_sync(FULLM, exa_, s1 + 16); \
    ef[6] = __shfl_sync(FULLM, exa_, s0 + 24); ef[7] = __shfl_sync(FULLM, exa_, s1 + 24); \
    efb[0] = __shfl_sync(FULLM, exb_, s0);      efb[1] = __shfl_sync(FULLM, exb_, s1);      \
    efb[2] = __shfl_sync(FULLM, exb_, s0 + 8);  efb[3] = __shfl_sync(FULLM, exb_, s1 + 8);  \
    efb[4] = __shfl_sync(FULLM, exb_, s0 + 16); efb[5] = __shfl_sync(FULLM, exb_, s1 + 16); \
    efb[6] = __shfl_sync(FULLM, exb_, s0 + 24); efb[7] = __shfl_sync(FULLM, exb_, s1 + 24); \
} while (0)

// One dual-batch recursion step: 8 MMAs (4 n-tiles x 2 chained k-tiles) carry
// both chains; elementwise scale, optional per-batch renorm, repack to bf16.
#define MSTEP2(NORM_) do {                                                    \
    float p0_,p1_,q0_,q1_, p2_,p3_,q2_,q3_, p4_,p5_,q4_,q5_, p6_,p7_,q6_,q7_; \
    mma16(p0_,p1_,q0_,q1_, va[0],vb[0],va[1],vb[1],                           \
          Bf[0][0][0],Bf[0][0][1], 0.f,0.f,0.f,0.f);                          \
    mma16(p2_,p3_,q2_,q3_, va[0],vb[0],va[1],vb[1],                           \
          Bf[0][1][0],Bf[0][1][1], 0.f,0.f,0.f,0.f);                          \
    mma16(p4_,p5_,q4_,q5_, va[0],vb[0],va[1],vb[1],                           \
          Bf[0][2][0],Bf[0][2][1], 0.f,0.f,0.f,0.f);                          \
    mma16(p6_,p7_,q6_,q7_, va[0],vb[0],va[1],vb[1],                           \
          Bf[0][3][0],Bf[0][3][1], 0.f,0.f,0.f,0.f);                          \
    mma16(p0_,p1_,q0_,q1_, va[2],vb[2],va[3],vb[3],                           \
          Bf[1][0][0],Bf[1][0][1], p0_,p1_,q0_,q1_);                          \
    mma16(p2_,p3_,q2_,q3_, va[2],vb[2],va[3],vb[3],                           \
          Bf[1][1][0],Bf[1][1][1], p2_,p3_,q2_,q3_);                          \
    mma16(p4_,p5_,q4_,q5_, va[2],vb[2],va[3],vb[3],                           \
          Bf[1][2][0],Bf[1][2][1], p4_,p5_,q4_,q5_);                          \
    mma16(p6_,p7_,q6_,q7_, va[2],vb[2],va[3],vb[3],                           \
          Bf[1][3][0],Bf[1][3][1], p6_,p7_,q6_,q7_);                          \
    fv[0]=p0_*ef[0];  fv[1]=p1_*ef[1];  fv[2]=p2_*ef[2];  fv[3]=p3_*ef[3];    \
    fv[4]=p4_*ef[4];  fv[5]=p5_*ef[5];  fv[6]=p6_*ef[6];  fv[7]=p7_*ef[7];    \
    fw[0]=q0_*efb[0]; fw[1]=q1_*efb[1]; fw[2]=q2_*efb[2]; fw[3]=q3_*efb[3];   \
    fw[4]=q4_*efb[4]; fw[5]=q5_*efb[5]; fw[6]=q6_*efb[6]; fw[7]=q7_*efb[7];   \
    if (NORM_) {                                                              \
        float va0_ = __shfl_sync(FULLM, fv[0], 0);                            \
        float vb0_ = __shfl_sync(FULLM, fw[0], 0);                            \
        float ra_ = rcp_approx(va0_), rb_ = rcp_approx(vb0_);                 \
        Ml2a += lg2_approx(va0_);   Ml2b += lg2_approx(vb0_);                 \
        fv[0]*=ra_; fv[1]*=ra_; fv[2]*=ra_; fv[3]*=ra_;                       \
        fv[4]*=ra_; fv[5]*=ra_; fv[6]*=ra_; fv[7]*=ra_;                       \
        fw[0]*=rb_; fw[1]*=rb_; fw[2]*=rb_; fw[3]*=rb_;                       \
        fw[4]*=rb_; fw[5]*=rb_; fw[6]*=rb_; fw[7]*=rb_;                       \
    }                                                                         \
    va[0] = pack_bf16(fv[0], fv[1]); va[1] = pack_bf16(fv[2], fv[3]);         \
    va[2] = pack_bf16(fv[4], fv[5]); va[3] = pack_bf16(fv[6], fv[7]);         \
    vb[0] = pack_bf16(fw[0], fw[1]); vb[1] = pack_bf16(fw[2], fw[3]);         \
    vb[2] = pack_bf16(fw[4], fw[5]); vb[3] = pack_bf16(fw[6], fw[7]);         \
} while (0)

// Dual-batch half-chain: 1023 emission steps (+1 plain step for backward).
template<int SGN, bool TRANS>
__device__ __forceinline__ void run_half2(
    const float* __restrict__ ep0,   // batch0: em + start_row*CC + lane
    const float* __restrict__ ep1,   // batch1
    const float* __restrict__ transitions,
    float fvo[8], float fwo[8], float& mo_a, float& mo_b, int lane)
{
    const int tid = lane & 3;
    const int gid = lane >> 2;
    const int s0 = 2 * tid, s1 = 2 * tid + 1;

    // B fragments of W: fwd W[k][n] = exp(T[n][k]); bwd W[k][n] = exp(T[k][n])
    uint32_t Bf[2][4][2];
#pragma unroll
    for (int kt = 0; kt < 2; ++kt)
#pragma unroll
        for (int nt = 0; nt < 4; ++nt) {
            int n  = nt * 8 + gid;
            int k0 = kt * 16 + 2 * tid;
            float w00, w01, w10, w11;
            if (!TRANS) {
                w00 = __expf(transitions[n * CC + k0]);
                w01 = __expf(transitions[n * CC + k0 + 1]);
                w10 = __expf(transitions[n * CC + k0 + 8]);
                w11 = __expf(transitions[n * CC + k0 + 9]);
            } else {
                w00 = __expf(transitions[(k0)     * CC + n]);
                w01 = __expf(transitions[(k0 + 1) * CC + n]);
                w10 = __expf(transitions[(k0 + 8) * CC + n]);
                w11 = __expf(transitions[(k0 + 9) * CC + n]);
            }
            Bf[kt][nt][0] = pack_bf16(w00, w01);
            Bf[kt][nt][1] = pack_bf16(w10, w11);
        }

    // 8-deep raw-row prefetch per batch (lane = state, coalesced LDG.32)
    float ea[8], eb[8];
#pragma unroll
    for (int k = 0; k < 8; ++k) {
        ea[k] = ep0[(long)SGN * CC * (1 + k)];
        eb[k] = ep1[(long)SGN * CC * (1 + k)];
    }

    // v_init = exp(e_row0): row layout -> fragment layout -> normalize
    float fv[8], fw[8];
    float Ml2a, Ml2b;
    uint32_t va[4], vb[4];
    {
        float eva = ex2_approx(ep0[0] * LOG2E);
        float evb = ex2_approx(ep1[0] * LOG2E);
        fv[0] = __shfl_sync(FULLM, eva, s0);      fv[1] = __shfl_sync(FULLM, eva, s1);
        fv[2] = __shfl_sync(FULLM, eva, s0 + 8);  fv[3] = __shfl_sync(FULLM, eva, s1 + 8);
        fv[4] = __shfl_sync(FULLM, eva, s0 + 16); fv[5] = __shfl_sync(FULLM, eva, s1 + 16);
        fv[6] = __shfl_sync(FULLM, eva, s0 + 24); fv[7] = __shfl_sync(FULLM, eva, s1 + 24);
        fw[0] = __shfl_sync(FULLM, evb, s0);      fw[1] = __shfl_sync(FULLM, evb, s1);
        fw[2] = __shfl_sync(FULLM, evb, s0 + 8);  fw[3] = __shfl_sync(FULLM, evb, s1 + 8);
        fw[4] = __shfl_sync(FULLM, evb, s0 + 16); fw[5] = __shfl_sync(FULLM, evb, s1 + 16);
        fw[6] = __shfl_sync(FULLM, evb, s0 + 24); fw[7] = __shfl_sync(FULLM, evb, s1 + 24);
        float v0a = __shfl_sync(FULLM, eva, 0);
        float v0b = __shfl_sync(FULLM, evb, 0);
        float ra = rcp_approx(v0a), rb = rcp_approx(v0b);
        Ml2a = lg2_approx(v0a);  Ml2b = lg2_approx(v0b);
        va[0] = pack_bf16(fv[0]*ra, fv[1]*ra);  va[1] = pack_bf16(fv[2]*ra, fv[3]*ra);
        va[2] = pack_bf16(fv[4]*ra, fv[5]*ra);  va[3] = pack_bf16(fv[6]*ra, fv[7]*ra);
        vb[0] = pack_bf16(fw[0]*rb, fw[1]*rb);  vb[1] = pack_bf16(fw[2]*rb, fw[3]*rb);
        vb[2] = pack_bf16(fw[4]*rb, fw[5]*rb);  vb[3] = pack_bf16(fw[6]*rb, fw[7]*rb);
    }

    float ef[8], efb[8];
    PREPE2(ea[0], eb[0]);   // exp fragments for t = 1

    const float* pf0 = ep0 + (long)SGN * CC * 9;
    const float* pf1 = ep1 + (long)SGN * CC * 9;

    // main: t = 1..1016 (127 x 8). Normalize at t % 4 == 0 <=> k % 4 == 3.
#pragma unroll 1
    for (int blk = 0; blk < 127; ++blk) {
#pragma unroll
        for (int k = 0; k < 8; ++k) {
            float ra_ = ea[(k + 1) & 7];          // row t+1 (batch0)
            float rb_ = eb[(k + 1) & 7];          // row t+1 (batch1)
            ea[k] = pf0[(long)SGN * CC * k];      // refill row t+8
            eb[k] = pf1[(long)SGN * CC * k];
            MSTEP2((k & 3) == 3);
            PREPE2(ra_, rb_);
        }
        pf0 += (long)SGN * CC * 8;
        pf1 += (long)SGN * CC * 8;
    }
    // tail: t = 1017..1023 (ea/eb hold rows 1017..1024)
#pragma unroll
    for (int k = 0; k < 7; ++k) {
        float ra_ = ea[k + 1], rb_ = eb[k + 1];
        MSTEP2((k & 3) == 3);
        if (k < 6) PREPE2(ra_, rb_);
    }

    if (TRANS) {
        // backward extra step: plain W multiply (e = 1)
#pragma unroll
        for (int j = 0; j < 8; ++j) { ef[j] = 1.0f; efb[j] = 1.0f; }
        MSTEP2(false);
    }

#pragma unroll
    for (int j = 0; j < 8; ++j) { fvo[j] = fv[j]; fwo[j] = fw[j]; }
    mo_a = Ml2a;  mo_b = Ml2b;
}

__global__ void crf_init() {
    int i = threadIdx.x;
    if (i < BB) g_bt[i] = 0;
    if (i == BB) g_ticket = 0;
}

// Second-arriving half computes log_Z; last global ticket reduces the mean.
__device__ __forceinline__ void merge_and_finish(int b, int lane, float* out) {
    int second = 0;
    if (lane == 0) {
        __threadfence();
        second = (atomicAdd(&g_bt[b], 1) == 1);
    }
    second = __shfl_sync(FULLM, second, 0);
    if (second) {
        __threadfence();
        float w = __ldcg(&g_w[b * CC + lane]);
        float u = __ldcg(&g_u[b * CC + lane]);
        float p = w * u;
#pragma unroll
        for (int o = 16; o; o >>= 1) p += __shfl_xor_sync(FULLM, p, o);
        if (lane == 0) {
            float mf = __ldcg(&g_mf[b]);
            float mb = __ldcg(&g_mb[b]);
            g_logz[b] = (double)(mf + mb) * 0.6931471805599453 + log((double)p);
        }
    } else return;

    int is_last = 0;
    if (lane == 0) {
        __threadfence();
        is_last = (atomicAdd(&g_ticket, 1) == 2 * BB - 1);
    }
    is_last = __shfl_sync(FULLM, is_last, 0);
    if (is_last) {
        __threadfence();
        double acc = 0.0;
        for (int i = lane; i < BB; i += 32)
            acc += __ldcg(&g_logz[i]) - __ldcg(&g_score[i]);
#pragma unroll
        for (int o = 16; o; o >>= 1) acc += __shfl_xor_sync(FULLM, acc, o);
        if (lane == 0) out[0] = (float)(acc / (double)BB);
    }
}

// Blocks 0..255: forward halves (batches 2i, 2i+1).
// Blocks 256..511: backward halves (batches 2(i-256), +1).
// Blocks 512..1023: path score (batch bid-512).
__global__ void __launch_bounds__(CC) crf_main(
    const float* __restrict__ emissions,
    const float* __restrict__ transitions,
    const int*   __restrict__ tags,
    const int*   __restrict__ mask,
    float*       __restrict__ out)
{
    const int lane = threadIdx.x;
    const int bid  = blockIdx.x;

    if (bid < BB) {
        const bool isFwd = bid < (BB / 2);
        const int  i     = isFwd ? bid : bid - BB / 2;
        const int  b0    = 2 * i, b1 = 2 * i + 1;
        const float* em0 = emissions + (size_t)b0 * (LL * CC);
        const float* em1 = emissions + (size_t)b1 * (LL * CC);

        float fv[8], fw[8];
        float m0, m1;
        if (isFwd) {
            run_half2<+1, false>(em0 + lane, em1 + lane, transitions,
                                 fv, fw, m0, m1, lane);
        } else {
            const size_t off = (size_t)(LL - 1) * CC;
            run_half2<-1, true>(em0 + off + lane, em1 + off + lane, transitions,
                                fv, fw, m0, m1, lane);
        }

        // store half-vectors (fragment layout mirrored across groups;
        // lanes 0-3 = group 0 write cols 8j+2*lane, 8j+2*lane+1)
        float* dst = isFwd ? g_w : g_u;
        if (lane < 4) {
#pragma unroll
            for (int j = 0; j < 4; ++j) {
                dst[b0 * CC + 8 * j + 2 * lane]     = fv[2 * j];
                dst[b0 * CC + 8 * j + 2 * lane + 1] = fv[2 * j + 1];
                dst[b1 * CC + 8 * j + 2 * lane]     = fw[2 * j];
                dst[b1 * CC + 8 * j + 2 * lane + 1] = fw[2 * j + 1];
            }
        }
        if (lane == 0) {
            float* ms = isFwd ? g_mf : g_mb;
            ms[b0] = m0;  ms[b1] = m1;
        }
        merge_and_finish(b0, lane, out);
        merge_and_finish(b1, lane, out);
    } else {
        // ============ path score ============
        const int b = bid - BB;
        const int* tg = tags + (size_t)b * LL;
        const int* mk = mask + (size_t)b * LL;
        const float* eb = emissions + (size_t)b * (LL * CC);

        int ms = 0;
        for (int t = lane; t < LL; t += 32) ms += mk[t];
#pragma unroll
        for (int o = 16; o; o >>= 1) ms += __shfl_xor_sync(FULLM, ms, o);

        double acc = 0.0;
        for (int t = lane; t < LL - 1; t += 32) {
            int a = tg[t], c = tg[t + 1];
            float m0 = (float)mk[t], m1 = (float)mk[t + 1];
            acc += (double)(eb[t * CC + a] * m0)
                 + (double)(transitions[a * CC + c] * m1);
        }
#pragma unroll
        for (int o = 16; o; o >>= 1) acc += __shfl_xor_sync(FULLM, acc, o);

        if (lane == 0) {
            int last_idx = ms - 1; if (last_idx < 0) last_idx = 0;
            int msc = ms; if (msc < 1) msc = 1;
            int le_t = msc - 1;
            int last_tag = tg[last_idx];
            acc += (double)eb[le_t * CC + last_tag];
            g_score[b] = acc;
        }

        int is_last = 0;
        if (lane == 0) {
            __threadfence();
            is_last = (atomicAdd(&g_ticket, 1) == 2 * BB - 1);
        }
        is_last = __shfl_sync(FULLM, is_last, 0);
        if (is_last) {
            __threadfence();
            double acc2 = 0.0;
            for (int i = lane; i < BB; i += 32)
                acc2 += __ldcg(&g_logz[i]) - __ldcg(&g_score[i]);
#pragma unroll
            for (int o = 16; o; o >>= 1) acc2 += __shfl_xor_sync(FULLM, acc2, o);
            if (lane == 0) out[0] = (float)(acc2 / (double)BB);
        }
    }
}

extern "C" void kernel_launch(void* const* d_in, const int* in_sizes, int n_in,
                              void* d_out, int out_size) {
    const float* emissions   = (const float*)d_in[0];
    const float* transitions = (const float*)d_in[1];
    const int*   tags        = (const int*)d_in[2];
    const int*   mask        = (const int*)d_in[3];
    (void)in_sizes; (void)n_in; (void)out_size;

    crf_init<<<1, BB + 32>>>();
    crf_main<<<2 * BB, CC>>>(emissions, transitions, tags, mask, (float*)d_out);
}

// round 12
// speedup vs baseline: 1.4975x; 1.4975x over previous
#include <cuda_runtime.h>
#include <cuda_bf16.h>
#include <cstdint>

#define BB 512
#define LL 2048
#define CC 32

// Device scratch (no allocation allowed)
__device__ double g_logz[BB];
__device__ double g_score[BB];
__device__ float  g_w[BB * CC];   // forward half-vector
__device__ float  g_u[BB * CC];   // backward half-vector
__device__ float  g_mf[BB];       // forward log2-scale
__device__ float  g_mb[BB];       // backward log2-scale
__device__ int    g_bt[BB];       // per-batch merge ticket
__device__ int    g_ticket;       // global completion ticket

__device__ __forceinline__ float rcp_approx(float x) {
    float r; asm("rcp.approx.f32 %0, %1;" : "=f"(r) : "f"(x)); return r;
}
__device__ __forceinline__ float ex2_approx(float x) {
    float r; asm("ex2.approx.f32 %0, %1;" : "=f"(r) : "f"(x)); return r;
}
__device__ __forceinline__ float lg2_approx(float x) {
    float r; asm("lg2.approx.f32 %0, %1;" : "=f"(r) : "f"(x)); return r;
}
// pack(lo, hi) -> bf16x2 reg (hi in [31:16], lo in [15:0])
__device__ __forceinline__ uint32_t pack_bf16(float lo, float hi) {
    uint32_t r;
    asm("cvt.rn.satfinite.bf16x2.f32 %0, %1, %2;" : "=r"(r) : "f"(hi), "f"(lo));
    return r;
}
// m16n8k16 bf16 MMA, A rows 8-15 zeroed (a1=a3=0), C = 0 -> pure product.
__device__ __forceinline__ void mma8z(float& d0, float& d1,
    uint32_t a0, uint32_t a2, uint32_t b0, uint32_t b1)
{
    float dz2, dz3;
    asm("mma.sync.aligned.m16n8k16.row.col.f32.bf16.bf16.f32 "
        "{%0,%1,%2,%3}, {%4,%5,%6,%7}, {%8,%9}, {%10,%11,%12,%13};"
        : "=f"(d0), "=f"(d1), "=f"(dz2), "=f"(dz3)
        : "r"(a0), "r"(0u), "r"(a2), "r"(0u),
          "r"(b0), "r"(b1),
          "f"(0.f), "f"(0.f), "f"(0.f), "f"(0.f));
}

#define LOG2E 1.4426950408889634f
#define FULLM 0xffffffffu

// Prepare exp(emission) in FRAGMENT layout for the next step, from a raw
// row-layout value (lane = state): 1 warp-wide ex2 + 8 SHFL.IDX.
// Runs one step ahead -> entirely off the MMA critical path.
#define PREPE(RAW_) do {                                                      \
    float ex_ = ex2_approx((RAW_) * LOG2E);                                   \
    ef[0] = __shfl_sync(FULLM, ex_, s0);       ef[1] = __shfl_sync(FULLM, ex_, s1);       \
    ef[2] = __shfl_sync(FULLM, ex_, s0 + 8);   ef[3] = __shfl_sync(FULLM, ex_, s1 + 8);   \
    ef[4] = __shfl_sync(FULLM, ex_, s0 + 16);  ef[5] = __shfl_sync(FULLM, ex_, s1 + 16);  \
    ef[6] = __shfl_sync(FULLM, ex_, s0 + 24);  ef[7] = __shfl_sync(FULLM, ex_, s1 + 24);  \
} while (0)

// One recursion step: 8 INDEPENDENT MMAs (4 n-tiles x 2 k-tiles, separate
// accumulators — no D->C chaining, halves the HMMA latency chain), FADD merge,
// elementwise scale by precomputed ef, optional renorm, repack to bf16.
#define MSTEP(NORM_) do {                                                     \
    float e0_,e1_,e2_,e3_,e4_,e5_,e6_,e7_;                                    \
    float f0_,f1_,f2_,f3_,f4_,f5_,f6_,f7_;                                    \
    mma8z(e0_,e1_, va[0],va[1], Bf[0][0][0],Bf[0][0][1]);                     \
    mma8z(f0_,f1_, va[2],va[3], Bf[1][0][0],Bf[1][0][1]);                     \
    mma8z(e2_,e3_, va[0],va[1], Bf[0][1][0],Bf[0][1][1]);                     \
    mma8z(f2_,f3_, va[2],va[3], Bf[1][1][0],Bf[1][1][1]);                     \
    mma8z(e4_,e5_, va[0],va[1], Bf[0][2][0],Bf[0][2][1]);                     \
    mma8z(f4_,f5_, va[2],va[3], Bf[1][2][0],Bf[1][2][1]);                     \
    mma8z(e6_,e7_, va[0],va[1], Bf[0][3][0],Bf[0][3][1]);                     \
    mma8z(f6_,f7_, va[2],va[3], Bf[1][3][0],Bf[1][3][1]);                     \
    fv[0]=(e0_+f0_)*ef[0]; fv[1]=(e1_+f1_)*ef[1];                             \
    fv[2]=(e2_+f2_)*ef[2]; fv[3]=(e3_+f3_)*ef[3];                             \
    fv[4]=(e4_+f4_)*ef[4]; fv[5]=(e5_+f5_)*ef[5];                             \
    fv[6]=(e6_+f6_)*ef[6]; fv[7]=(e7_+f7_)*ef[7];                             \
    if (NORM_) {                                                              \
        float v0_ = __shfl_sync(FULLM, fv[0], 0);                             \
        float r_  = rcp_approx(v0_);                                          \
        Ml2 += lg2_approx(v0_);                                               \
        fv[0]*=r_; fv[1]*=r_; fv[2]*=r_; fv[3]*=r_;                           \
        fv[4]*=r_; fv[5]*=r_; fv[6]*=r_; fv[7]*=r_;                           \
    }                                                                         \
    va[0] = pack_bf16(fv[0], fv[1]); va[1] = pack_bf16(fv[2], fv[3]);         \
    va[2] = pack_bf16(fv[4], fv[5]); va[3] = pack_bf16(fv[6], fv[7]);         \
} while (0)

// One half-chain: 1023 emission steps (+1 plain T^T step for backward).
// SGN = +1 forward / -1 backward (compile-time addressing).
// TRANS: B = exp(T)^T (fwd) or exp(T) (bwd).
template<int SGN, bool TRANS>
__device__ __forceinline__ float run_half(
    const float* __restrict__ ep,          // em + start_row*CC + lane
    const float* __restrict__ transitions,
    float fv_out[8], int lane)
{
    const int tid = lane & 3;
    const int gid = lane >> 2;
    const int s0 = 2 * tid, s1 = 2 * tid + 1;

    // B fragments of W: fwd W[k][n] = exp(T[n][k]); bwd W[k][n] = exp(T[k][n])
    uint32_t Bf[2][4][2];
#pragma unroll
    for (int kt = 0; kt < 2; ++kt)
#pragma unroll
        for (int nt = 0; nt < 4; ++nt) {
            int n  = nt * 8 + gid;
            int k0 = kt * 16 + 2 * tid;
            float w00, w01, w10, w11;
            if (!TRANS) {
                w00 = __expf(transitions[n * CC + k0]);
                w01 = __expf(transitions[n * CC + k0 + 1]);
                w10 = __expf(transitions[n * CC + k0 + 8]);
                w11 = __expf(transitions[n * CC + k0 + 9]);
            } else {
                w00 = __expf(transitions[(k0)     * CC + n]);
                w01 = __expf(transitions[(k0 + 1) * CC + n]);
                w10 = __expf(transitions[(k0 + 8) * CC + n]);
                w11 = __expf(transitions[(k0 + 9) * CC + n]);
            }
            Bf[kt][nt][0] = pack_bf16(w00, w01);
            Bf[kt][nt][1] = pack_bf16(w10, w11);
        }

    // 8-deep raw-row prefetch (lane = state, coalesced LDG.32)
    float ebuf[8];
#pragma unroll
    for (int k = 0; k < 8; ++k) ebuf[k] = ep[(long)SGN * CC * (1 + k)];

    // v_init = exp(e_row0): row layout -> fragment layout -> normalize
    float ev0 = ex2_approx(ep[0] * LOG2E);
    float fv[8];
    fv[0] = __shfl_sync(FULLM, ev0, s0);       fv[1] = __shfl_sync(FULLM, ev0, s1);
    fv[2] = __shfl_sync(FULLM, ev0, s0 + 8);   fv[3] = __shfl_sync(FULLM, ev0, s1 + 8);
    fv[4] = __shfl_sync(FULLM, ev0, s0 + 16);  fv[5] = __shfl_sync(FULLM, ev0, s1 + 16);
    fv[6] = __shfl_sync(FULLM, ev0, s0 + 24);  fv[7] = __shfl_sync(FULLM, ev0, s1 + 24);
    float v0i = __shfl_sync(FULLM, ev0, 0);
    float rri = rcp_approx(v0i);
    float Ml2 = lg2_approx(v0i);
    uint32_t va[4];
    va[0] = pack_bf16(fv[0]*rri, fv[1]*rri);  va[1] = pack_bf16(fv[2]*rri, fv[3]*rri);
    va[2] = pack_bf16(fv[4]*rri, fv[5]*rri);  va[3] = pack_bf16(fv[6]*rri, fv[7]*rri);

    float ef[8];
    PREPE(ebuf[0]);   // exp fragment for t = 1

    const float* pf = ep + (long)SGN * CC * 9;

    // main: t = 1..1016 (127 x 8). Normalize at t % 4 == 0 <=> k % 4 == 3.
#pragma unroll 1
    for (int blk = 0; blk < 127; ++blk) {
#pragma unroll
        for (int k = 0; k < 8; ++k) {
            float rawn = ebuf[(k + 1) & 7];       // row t+1
            ebuf[k] = pf[(long)SGN * CC * k];     // refill row t+8
            MSTEP((k & 3) == 3);
            PREPE(rawn);
        }
        pf += (long)SGN * CC * 8;
    }
    // tail: t = 1017..1023 (ebuf holds rows 1017..1024)
#pragma unroll
    for (int k = 0; k < 7; ++k) {
        float rawn = ebuf[k + 1];
        MSTEP((k & 3) == 3);
        if (k < 6) PREPE(rawn);
    }

    if (TRANS) {
        // backward extra step: plain W multiply (e = 1)
#pragma unroll
        for (int j = 0; j < 8; ++j) ef[j] = 1.0f;
        MSTEP(false);
    }

#pragma unroll
    for (int j = 0; j < 8; ++j) fv_out[j] = fv[j];
    return Ml2;
}

__global__ void crf_init() {
    int i = threadIdx.x;
    if (i < BB) g_bt[i] = 0;
    if (i == BB) g_ticket = 0;
}

// Second-arriving half computes log_Z; last global ticket reduces the mean.
__device__ __forceinline__ void merge_and_finish(int b, int lane, float* out) {
    int second = 0;
    if (lane == 0) {
        __threadfence();
        second = (atomicAdd(&g_bt[b], 1) == 1);
    }
    second = __shfl_sync(FULLM, second, 0);
    if (second) {
        __threadfence();
        float w = __ldcg(&g_w[b * CC + lane]);
        float u = __ldcg(&g_u[b * CC + lane]);
        float p = w * u;
#pragma unroll
        for (int o = 16; o; o >>= 1) p += __shfl_xor_sync(FULLM, p, o);
        if (lane == 0) {
            float mf = __ldcg(&g_mf[b]);
            float mb = __ldcg(&g_mb[b]);
            g_logz[b] = (double)(mf + mb) * 0.6931471805599453 + log((double)p);
        }
    } else return;

    int is_last = 0;
    if (lane == 0) {
        __threadfence();
        is_last = (atomicAdd(&g_ticket, 1) == 2 * BB - 1);
    }
    is_last = __shfl_sync(FULLM, is_last, 0);
    if (is_last) {
        __threadfence();
        double acc = 0.0;
        for (int i = lane; i < BB; i += 32)
            acc += __ldcg(&g_logz[i]) - __ldcg(&g_score[i]);
#pragma unroll
        for (int o = 16; o; o >>= 1) acc += __shfl_xor_sync(FULLM, acc, o);
        if (lane == 0) out[0] = (float)(acc / (double)BB);
    }
}

// Blocks 0..511: forward half (t=1..1023). Blocks 512..1023: backward half
// (t=2047..1024, transposed). Blocks 1024..1535: path score.
__global__ void __launch_bounds__(CC) crf_main(
    const float* __restrict__ emissions,
    const float* __restrict__ transitions,
    const int*   __restrict__ tags,
    const int*   __restrict__ mask,
    float*       __restrict__ out)
{
    const int lane = threadIdx.x;
    const int bid  = blockIdx.x;

    if (bid < 2 * BB) {
        const int  b     = bid & (BB - 1);
        const bool isFwd = bid < BB;
        const float* em  = emissions + (size_t)b * (LL * CC);

        float fv[8];
        float Ml2;
        if (isFwd) {
            Ml2 = run_half<+1, false>(em + lane, transitions, fv, lane);
        } else {
            Ml2 = run_half<-1, true>(em + (size_t)(LL - 1) * CC + lane,
                                     transitions, fv, lane);
        }

        // store half-vector (fragment layout mirrored across groups; lanes 0-3
        // = group 0 write cols 8j+2*lane, 8j+2*lane+1)
        float* dst = isFwd ? g_w : g_u;
        if (lane < 4) {
#pragma unroll
            for (int j = 0; j < 4; ++j) {
                dst[b * CC + 8 * j + 2 * lane]     = fv[2 * j];
                dst[b * CC + 8 * j + 2 * lane + 1] = fv[2 * j + 1];
            }
        }
        if (lane == 0) { (isFwd ? g_mf : g_mb)[b] = Ml2; }
        merge_and_finish(b, lane, out);
    } else {
        // ============ path score ============
        const int b = bid - 2 * BB;
        const int* tg = tags + (size_t)b * LL;
        const int* mk = mask + (size_t)b * LL;
        const float* eb = emissions + (size_t)b * (LL * CC);

        int ms = 0;
        for (int t = lane; t < LL; t += 32) ms += mk[t];
#pragma unroll
        for (int o = 16; o; o >>= 1) ms += __shfl_xor_sync(FULLM, ms, o);

        double acc = 0.0;
        for (int t = lane; t < LL - 1; t += 32) {
            int a = tg[t], c = tg[t + 1];
            float m0 = (float)mk[t], m1 = (float)mk[t + 1];
            acc += (double)(eb[t * CC + a] * m0)
                 + (double)(transitions[a * CC + c] * m1);
        }
#pragma unroll
        for (int o = 16; o; o >>= 1) acc += __shfl_xor_sync(FULLM, acc, o);

        if (lane == 0) {
            int last_idx = ms - 1; if (last_idx < 0) last_idx = 0;
            int msc = ms; if (msc < 1) msc = 1;
            int le_t = msc - 1;
            int last_tag = tg[last_idx];
            acc += (double)eb[le_t * CC + last_tag];
            g_score[b] = acc;
        }

        int is_last = 0;
        if (lane == 0) {
            __threadfence();
            is_last = (atomicAdd(&g_ticket, 1) == 2 * BB - 1);
        }
        is_last = __shfl_sync(FULLM, is_last, 0);
        if (is_last) {
            __threadfence();
            double acc2 = 0.0;
            for (int i = lane; i < BB; i += 32)
                acc2 += __ldcg(&g_logz[i]) - __ldcg(&g_score[i]);
#pragma unroll
            for (int o = 16; o; o >>= 1) acc2 += __shfl_xor_sync(FULLM, acc2, o);
            if (lane == 0) out[0] = (float)(acc2 / (double)BB);
        }
    }
}

extern "C" void kernel_launch(void* const* d_in, const int* in_sizes, int n_in,
                              void* d_out, int out_size) {
    const float* emissions   = (const float*)d_in[0];
    const float* transitions = (const float*)d_in[1];
    const int*   tags        = (const int*)d_in[2];
    const int*   mask        = (const int*)d_in[3];
    (void)in_sizes; (void)n_in; (void)out_size;

    crf_init<<<1, BB + 32>>>();
    crf_main<<<3 * BB, CC>>>(emissions, transitions, tags, mask, (float*)d_out);
}

// round 13
// speedup vs baseline: 1.5152x; 1.0118x over previous
#include <cuda_runtime.h>
#include <cuda_bf16.h>
#include <cstdint>

#define BB 512
#define LL 2048
#define CC 32

// Device scratch (no allocation allowed)
__device__ double g_logz[BB];
__device__ double g_score[BB];
__device__ float  g_w[BB * CC];   // forward half-vector
__device__ float  g_u[BB * CC];   // backward half-vector
__device__ float  g_mf[BB];       // forward log2-scale
__device__ float  g_mb[BB];       // backward log2-scale
__device__ int    g_bt[BB];       // per-batch merge ticket
__device__ int    g_ticket;       // global completion ticket

__device__ __forceinline__ float rcp_approx(float x) {
    float r; asm("rcp.approx.f32 %0, %1;" : "=f"(r) : "f"(x)); return r;
}
__device__ __forceinline__ float ex2_approx(float x) {
    float r; asm("ex2.approx.f32 %0, %1;" : "=f"(r) : "f"(x)); return r;
}
__device__ __forceinline__ float lg2_approx(float x) {
    float r; asm("lg2.approx.f32 %0, %1;" : "=f"(r) : "f"(x)); return r;
}
// pack(lo, hi) -> bf16x2 reg (hi in [31:16], lo in [15:0])
__device__ __forceinline__ uint32_t pack_bf16(float lo, float hi) {
    uint32_t r;
    asm("cvt.rn.satfinite.bf16x2.f32 %0, %1, %2;" : "=r"(r) : "f"(hi), "f"(lo));
    return r;
}
// m16n8k16 bf16 MMA, A rows 8-15 zeroed (a1=a3=0), C = 0 -> pure product.
__device__ __forceinline__ void mma8z(float& d0, float& d1,
    uint32_t a0, uint32_t a2, uint32_t b0, uint32_t b1)
{
    float dz2, dz3;
    asm("mma.sync.aligned.m16n8k16.row.col.f32.bf16.bf16.f32 "
        "{%0,%1,%2,%3}, {%4,%5,%6,%7}, {%8,%9}, {%10,%11,%12,%13};"
        : "=f"(d0), "=f"(d1), "=f"(dz2), "=f"(dz3)
        : "r"(a0), "r"(0u), "r"(a2), "r"(0u),
          "r"(b0), "r"(b1),
          "f"(0.f), "f"(0.f), "f"(0.f), "f"(0.f));
}

#define LOG2E 1.4426950408889634f
#define FULLM 0xffffffffu

// Prepare exp(emission) in FRAGMENT layout for the next step, from a raw
// row-layout value (lane = state): 1 warp-wide ex2 + 8 SHFL.IDX.
// Runs one step ahead -> entirely off the MMA critical path.
#define PREPE(RAW_) do {                                                      \
    float ex_ = ex2_approx((RAW_) * LOG2E);                                   \
    ef[0] = __shfl_sync(FULLM, ex_, s0);       ef[1] = __shfl_sync(FULLM, ex_, s1);       \
    ef[2] = __shfl_sync(FULLM, ex_, s0 + 8);   ef[3] = __shfl_sync(FULLM, ex_, s1 + 8);   \
    ef[4] = __shfl_sync(FULLM, ex_, s0 + 16);  ef[5] = __shfl_sync(FULLM, ex_, s1 + 16);  \
    ef[6] = __shfl_sync(FULLM, ex_, s0 + 24);  ef[7] = __shfl_sync(FULLM, ex_, s1 + 24);  \
} while (0)

// One recursion step: 8 INDEPENDENT MMAs (4 n-tiles x 2 k-tiles, separate
// accumulators — no D->C chaining, halves the HMMA latency chain), FADD merge,
// elementwise scale by precomputed ef, optional renorm, repack to bf16.
#define MSTEP(NORM_) do {                                                     \
    float e0_,e1_,e2_,e3_,e4_,e5_,e6_,e7_;                                    \
    float f0_,f1_,f2_,f3_,f4_,f5_,f6_,f7_;                                    \
    mma8z(e0_,e1_, va[0],va[1], Bf[0][0][0],Bf[0][0][1]);                     \
    mma8z(f0_,f1_, va[2],va[3], Bf[1][0][0],Bf[1][0][1]);                     \
    mma8z(e2_,e3_, va[0],va[1], Bf[0][1][0],Bf[0][1][1]);                     \
    mma8z(f2_,f3_, va[2],va[3], Bf[1][1][0],Bf[1][1][1]);                     \
    mma8z(e4_,e5_, va[0],va[1], Bf[0][2][0],Bf[0][2][1]);                     \
    mma8z(f4_,f5_, va[2],va[3], Bf[1][2][0],Bf[1][2][1]);                     \
    mma8z(e6_,e7_, va[0],va[1], Bf[0][3][0],Bf[0][3][1]);                     \
    mma8z(f6_,f7_, va[2],va[3], Bf[1][3][0],Bf[1][3][1]);                     \
    fv[0]=(e0_+f0_)*ef[0]; fv[1]=(e1_+f1_)*ef[1];                             \
    fv[2]=(e2_+f2_)*ef[2]; fv[3]=(e3_+f3_)*ef[3];                             \
    fv[4]=(e4_+f4_)*ef[4]; fv[5]=(e5_+f5_)*ef[5];                             \
    fv[6]=(e6_+f6_)*ef[6]; fv[7]=(e7_+f7_)*ef[7];                             \
    if (NORM_) {                                                              \
        float v0_ = __shfl_sync(FULLM, fv[0], 0);                             \
        float r_  = rcp_approx(v0_);                                          \
        Ml2 += lg2_approx(v0_);                                               \
        fv[0]*=r_; fv[1]*=r_; fv[2]*=r_; fv[3]*=r_;                           \
        fv[4]*=r_; fv[5]*=r_; fv[6]*=r_; fv[7]*=r_;                           \
    }                                                                         \
    va[0] = pack_bf16(fv[0], fv[1]); va[1] = pack_bf16(fv[2], fv[3]);         \
    va[2] = pack_bf16(fv[4], fv[5]); va[3] = pack_bf16(fv[6], fv[7]);         \
} while (0)

// One half-chain: 1023 emission steps (+1 plain T^T step for backward).
// SGN = +1 forward / -1 backward (compile-time addressing).
// TRANS: B = exp(T)^T (fwd) or exp(T) (bwd).
template<int SGN, bool TRANS>
__device__ __forceinline__ float run_half(
    const float* __restrict__ ep,          // em + start_row*CC + lane
    const float* __restrict__ transitions,
    float fv_out[8], int lane)
{
    const int tid = lane & 3;
    const int gid = lane >> 2;
    const int s0 = 2 * tid, s1 = 2 * tid + 1;

    // B fragments of W: fwd W[k][n] = exp(T[n][k]); bwd W[k][n] = exp(T[k][n])
    uint32_t Bf[2][4][2];
#pragma unroll
    for (int kt = 0; kt < 2; ++kt)
#pragma unroll
        for (int nt = 0; nt < 4; ++nt) {
            int n  = nt * 8 + gid;
            int k0 = kt * 16 + 2 * tid;
            float w00, w01, w10, w11;
            if (!TRANS) {
                w00 = __expf(transitions[n * CC + k0]);
                w01 = __expf(transitions[n * CC + k0 + 1]);
                w10 = __expf(transitions[n * CC + k0 + 8]);
                w11 = __expf(transitions[n * CC + k0 + 9]);
            } else {
                w00 = __expf(transitions[(k0)     * CC + n]);
                w01 = __expf(transitions[(k0 + 1) * CC + n]);
                w10 = __expf(transitions[(k0 + 8) * CC + n]);
                w11 = __expf(transitions[(k0 + 9) * CC + n]);
            }
            Bf[kt][nt][0] = pack_bf16(w00, w01);
            Bf[kt][nt][1] = pack_bf16(w10, w11);
        }

    // 8-deep raw-row prefetch (lane = state, coalesced LDG.32)
    float ebuf[8];
#pragma unroll
    for (int k = 0; k < 8; ++k) ebuf[k] = ep[(long)SGN * CC * (1 + k)];

    // v_init = exp(e_row0): row layout -> fragment layout -> normalize
    float ev0 = ex2_approx(ep[0] * LOG2E);
    float fv[8];
    fv[0] = __shfl_sync(FULLM, ev0, s0);       fv[1] = __shfl_sync(FULLM, ev0, s1);
    fv[2] = __shfl_sync(FULLM, ev0, s0 + 8);   fv[3] = __shfl_sync(FULLM, ev0, s1 + 8);
    fv[4] = __shfl_sync(FULLM, ev0, s0 + 16);  fv[5] = __shfl_sync(FULLM, ev0, s1 + 16);
    fv[6] = __shfl_sync(FULLM, ev0, s0 + 24);  fv[7] = __shfl_sync(FULLM, ev0, s1 + 24);
    float v0i = __shfl_sync(FULLM, ev0, 0);
    float rri = rcp_approx(v0i);
    float Ml2 = lg2_approx(v0i);
    uint32_t va[4];
    va[0] = pack_bf16(fv[0]*rri, fv[1]*rri);  va[1] = pack_bf16(fv[2]*rri, fv[3]*rri);
    va[2] = pack_bf16(fv[4]*rri, fv[5]*rri);  va[3] = pack_bf16(fv[6]*rri, fv[7]*rri);

    float ef[8];
    PREPE(ebuf[0]);   // exp fragment for t = 1

    const float* pf = ep + (long)SGN * CC * 9;

    // main: t = 1..1016 (127 x 8). Normalize at t % 4 == 0 <=> k % 4 == 3.
#pragma unroll 1
    for (int blk = 0; blk < 127; ++blk) {
#pragma unroll
        for (int k = 0; k < 8; ++k) {
            float rawn = ebuf[(k + 1) & 7];       // row t+1
            ebuf[k] = pf[(long)SGN * CC * k];     // refill row t+8
            MSTEP((k & 3) == 3);
            PREPE(rawn);
        }
        pf += (long)SGN * CC * 8;
    }
    // tail: t = 1017..1023 (ebuf holds rows 1017..1024)
#pragma unroll
    for (int k = 0; k < 7; ++k) {
        float rawn = ebuf[k + 1];
        MSTEP((k & 3) == 3);
        if (k < 6) PREPE(rawn);
    }

    if (TRANS) {
        // backward extra step: plain W multiply (e = 1)
#pragma unroll
        for (int j = 0; j < 8; ++j) ef[j] = 1.0f;
        MSTEP(false);
    }

#pragma unroll
    for (int j = 0; j < 8; ++j) fv_out[j] = fv[j];
    return Ml2;
}

__global__ void crf_init() {
    int i = threadIdx.x;
    if (i < BB) g_bt[i] = 0;
    if (i == BB) g_ticket = 0;
}

// Second-arriving half computes log_Z; last global ticket reduces the mean.
__device__ __forceinline__ void merge_and_finish(int b, int lane, float* out) {
    int second = 0;
    if (lane == 0) {
        __threadfence();
        second = (atomicAdd(&g_bt[b], 1) == 1);
    }
    second = __shfl_sync(FULLM, second, 0);
    if (second) {
        __threadfence();
        float w = __ldcg(&g_w[b * CC + lane]);
        float u = __ldcg(&g_u[b * CC + lane]);
        float p = w * u;
#pragma unroll
        for (int o = 16; o; o >>= 1) p += __shfl_xor_sync(FULLM, p, o);
        if (lane == 0) {
            float mf = __ldcg(&g_mf[b]);
            float mb = __ldcg(&g_mb[b]);
            g_logz[b] = (double)(mf + mb) * 0.6931471805599453 + log((double)p);
        }
    } else return;

    int is_last = 0;
    if (lane == 0) {
        __threadfence();
        is_last = (atomicAdd(&g_ticket, 1) == 2 * BB - 1);
    }
    is_last = __shfl_sync(FULLM, is_last, 0);
    if (is_last) {
        __threadfence();
        double acc = 0.0;
        for (int i = lane; i < BB; i += 32)
            acc += __ldcg(&g_logz[i]) - __ldcg(&g_score[i]);
#pragma unroll
        for (int o = 16; o; o >>= 1) acc += __shfl_xor_sync(FULLM, acc, o);
        if (lane == 0) out[0] = (float)(acc / (double)BB);
    }
}

// Blocks 0..511: forward half (t=1..1023). Blocks 512..1023: backward half
// (t=2047..1024, transposed). Blocks 1024..1535: path score.
__global__ void __launch_bounds__(CC) crf_main(
    const float* __restrict__ emissions,
    const float* __restrict__ transitions,
    const int*   __restrict__ tags,
    const int*   __restrict__ mask,
    float*       __restrict__ out)
{
    const int lane = threadIdx.x;
    const int bid  = blockIdx.x;

    if (bid < 2 * BB) {
        const int  b     = bid & (BB - 1);
        const bool isFwd = bid < BB;
        const float* em  = emissions + (size_t)b * (LL * CC);

        float fv[8];
        float Ml2;
        if (isFwd) {
            Ml2 = run_half<+1, false>(em + lane, transitions, fv, lane);
        } else {
            Ml2 = run_half<-1, true>(em + (size_t)(LL - 1) * CC + lane,
                                     transitions, fv, lane);
        }

        // store half-vector (fragment layout mirrored across groups; lanes 0-3
        // = group 0 write cols 8j+2*lane, 8j+2*lane+1)
        float* dst = isFwd ? g_w : g_u;
        if (lane < 4) {
#pragma unroll
            for (int j = 0; j < 4; ++j) {
                dst[b * CC + 8 * j + 2 * lane]     = fv[2 * j];
                dst[b * CC + 8 * j + 2 * lane + 1] = fv[2 * j + 1];
            }
        }
        if (lane == 0) { (isFwd ? g_mf : g_mb)[b] = Ml2; }
        merge_and_finish(b, lane, out);
    } else {
        // ============ path score ============
        const int b = bid - 2 * BB;
        const int* tg = tags + (size_t)b * LL;
        const int* mk = mask + (size_t)b * LL;
        const float* eb = emissions + (size_t)b * (LL * CC);

        int ms = 0;
        for (int t = lane; t < LL; t += 32) ms += mk[t];
#pragma unroll
        for (int o = 16; o; o >>= 1) ms += __shfl_xor_sync(FULLM, ms, o);

        double acc = 0.0;
        for (int t = lane; t < LL - 1; t += 32) {
            int a = tg[t], c = tg[t + 1];
            float m0 = (float)mk[t], m1 = (float)mk[t + 1];
            acc += (double)(eb[t * CC + a] * m0)
                 + (double)(transitions[a * CC + c] * m1);
        }
#pragma unroll
        for (int o = 16; o; o >>= 1) acc += __shfl_xor_sync(FULLM, acc, o);

        if (lane == 0) {
            int last_idx = ms - 1; if (last_idx < 0) last_idx = 0;
            int msc = ms; if (msc < 1) msc = 1;
            int le_t = msc - 1;
            int last_tag = tg[last_idx];
            acc += (double)eb[le_t * CC + last_tag];
            g_score[b] = acc;
        }

        int is_last = 0;
        if (lane == 0) {
            __threadfence();
            is_last = (atomicAdd(&g_ticket, 1) == 2 * BB - 1);
        }
        is_last = __shfl_sync(FULLM, is_last, 0);
        if (is_last) {
            __threadfence();
            double acc2 = 0.0;
            for (int i = lane; i < BB; i += 32)
                acc2 += __ldcg(&g_logz[i]) - __ldcg(&g_score[i]);
#pragma unroll
            for (int o = 16; o; o >>= 1) acc2 += __shfl_xor_sync(FULLM, acc2, o);
            if (lane == 0) out[0] = (float)(acc2 / (double)BB);
        }
    }
}

extern "C" void kernel_launch(void* const* d_in, const int* in_sizes, int n_in,
                              void* d_out, int out_size) {
    const float* emissions   = (const float*)d_in[0];
    const float* transitions = (const float*)d_in[1];
    const int*   tags        = (const int*)d_in[2];
    const int*   mask        = (const int*)d_in[3];
    (void)in_sizes; (void)n_in; (void)out_size;

    crf_init<<<1, BB + 32>>>();
    crf_main<<<3 * BB, CC>>>(emissions, transitions, tags, mask, (float*)d_out);
}